// round 15
// baseline (speedup 1.0000x reference)
#include <cuda_runtime.h>
#include <cuda_fp16.h>
#include <math.h>

#define T_   512
#define B_   64
#define I_   256
#define H_   512
#define G4_  2048
#define O_   256
#define BH_  (B_*H_)
#define GREC 128

#define NX_   (T_*B_*I_)     // x elements
#define NW0_  (G4_*I_)       // W_ih0 elements
#define NW_   (G4_*H_)       // W_ih1 / W_hh* elements

// ---------------- scratch (device globals; no allocations anywhere) --------
// RULE (GB300/ATS pitfall): these symbols are referenced ONLY in device code.
static __device__ float    g_pre[(size_t)T_*B_*G4_];      // gate preacts
static __device__ __half   g_hhi[(size_t)(T_+1)*BH_];     // h hi (f16)
static __device__ __half   g_hlo[(size_t)(T_+1)*BH_];     // h lo (f16)
static __device__ __half   g_xhi[NX_],     g_xlo[NX_];    // split x
static __device__ __half   g_wih0hi[NW0_], g_wih0lo[NW0_];
static __device__ __half   g_whh0hi[NW_],  g_whh0lo[NW_];
static __device__ __half   g_wih1hi[NW_],  g_wih1lo[NW_];
static __device__ __half   g_whh1hi[NW_],  g_whh1lo[NW_];
static __device__ unsigned g_bar4[4*32];                  // per-b-group barriers

__device__ __forceinline__ float sigf(float x){ return 1.0f/(1.0f+expf(-x)); }

__global__ void reset_bar_k(){
    if (threadIdx.x < 4) g_bar4[threadIdx.x << 5] = 0u;
}

// One fused split: x, W_ih0, W_hh0, W_ih1, W_hh1 -> hi/lo symbol arrays
__global__ void split_all_k(const float* __restrict__ x,
                            const float* __restrict__ wih0,
                            const float* __restrict__ whh0,
                            const float* __restrict__ wih1,
                            const float* __restrict__ whh1)
{
    int i = blockIdx.x*blockDim.x + threadIdx.x;
    const float* src; __half* hi; __half* lo; int off;
    if (i < NX_)                        { src=x;    hi=g_xhi;    lo=g_xlo;    off=i; }
    else if (i < NX_+NW0_)              { src=wih0; hi=g_wih0hi; lo=g_wih0lo; off=i-NX_; }
    else if (i < NX_+NW0_+NW_)          { src=whh0; hi=g_whh0hi; lo=g_whh0lo; off=i-NX_-NW0_; }
    else if (i < NX_+NW0_+2*NW_)        { src=wih1; hi=g_wih1hi; lo=g_wih1lo; off=i-NX_-NW0_-NW_; }
    else if (i < NX_+NW0_+3*NW_)        { src=whh1; hi=g_whh1hi; lo=g_whh1lo; off=i-NX_-NW0_-2*NW_; }
    else return;
    float v = src[off];
    __half h = __float2half_rn(v);
    hi[off] = h;
    lo[off] = __float2half_rn(v - __half2float(h));
}

// ---------------- mma helpers (PROVEN) --------------------------------------
__device__ __forceinline__ unsigned smem_u32(const void* p){
    return (unsigned)__cvta_generic_to_shared(p);
}
__device__ __forceinline__ void ldsm_x4(const void* p, unsigned* r){
    asm volatile("ldmatrix.sync.aligned.m8n8.x4.shared.b16 {%0,%1,%2,%3}, [%4];"
        : "=r"(r[0]),"=r"(r[1]),"=r"(r[2]),"=r"(r[3]) : "r"(smem_u32(p)) : "memory");
}
__device__ __forceinline__ void ldsm_x2(const void* p, unsigned* r){
    asm volatile("ldmatrix.sync.aligned.m8n8.x2.shared.b16 {%0,%1}, [%2];"
        : "=r"(r[0]),"=r"(r[1]) : "r"(smem_u32(p)) : "memory");
}
__device__ __forceinline__ void mma16816(float* c, const unsigned* a, const unsigned* b){
    asm volatile("mma.sync.aligned.m16n8k16.row.col.f32.f16.f16.f32 "
        "{%0,%1,%2,%3}, {%4,%5,%6,%7}, {%8,%9}, {%0,%1,%2,%3};"
        : "+f"(c[0]),"+f"(c[1]),"+f"(c[2]),"+f"(c[3])
        : "r"(a[0]),"r"(a[1]),"r"(a[2]),"r"(a[3]),"r"(b[0]),"r"(b[1]));
}

// ---------------------------------------------------------------------------
// Pre-GEMM, split-f16 HMMA (PROVEN R12 structure; per-layer W symbols).
// __launch_bounds__(256,3): cap regs (~84) -> 3 CTAs/SM (was 2, occ 24%).
// g_pre[m,n] = A[m,K] . W[n,K]^T + b1[n] + b2[n]
// ---------------------------------------------------------------------------
template<int K, int LAYER>
__global__ void __launch_bounds__(256, 3)
gemm_pre_mma(const float* __restrict__ b1, const float* __restrict__ b2)
{
    const __half* Ahi_g = LAYER ? (g_hhi + BH_) : g_xhi;
    const __half* Alo_g = LAYER ? (g_hlo + BH_) : g_xlo;
    const __half* Whi_g = LAYER ? g_wih1hi : g_wih0hi;
    const __half* Wlo_g = LAYER ? g_wih1lo : g_wih0lo;

    __shared__ __align__(16) __half Ah[128][40], Al[128][40], Wh[64][40], Wl[64][40];
    const int tid  = threadIdx.x;
    const int n0   = blockIdx.x * 64;
    const int m0   = blockIdx.y * 128;
    const int wid  = tid >> 5, lane = tid & 31;
    const int wm   = wid & 3,  wn   = wid >> 2;
    const int g    = lane >> 2, tig = lane & 3;
    const int a_row = lane & 15, a_co = (lane >> 4) * 8;
    const int b_row = lane & 7,  b_co = ((lane >> 3) & 1) * 8;

    float acc[2][4][4];
    #pragma unroll
    for (int mt=0;mt<2;mt++)
        #pragma unroll
        for (int nt=0;nt<4;nt++)
            #pragma unroll
            for (int q=0;q<4;q++) acc[mt][nt][q] = 0.f;

    for (int k0 = 0; k0 < K; k0 += 32){
        #pragma unroll
        for (int j=0;j<2;j++){
            int idx = tid + j*256;
            int r = idx >> 2, cc = (idx & 3) * 8;
            *(uint4*)&Ah[r][cc] = *(const uint4*)&Ahi_g[(size_t)(m0+r)*K + k0 + cc];
            *(uint4*)&Al[r][cc] = *(const uint4*)&Alo_g[(size_t)(m0+r)*K + k0 + cc];
        }
        {
            int r = tid >> 2, cc = (tid & 3) * 8;
            *(uint4*)&Wh[r][cc] = *(const uint4*)&Whi_g[(size_t)(n0+r)*K + k0 + cc];
            *(uint4*)&Wl[r][cc] = *(const uint4*)&Wlo_g[(size_t)(n0+r)*K + k0 + cc];
        }
        __syncthreads();
        #pragma unroll
        for (int ks=0;ks<2;ks++){
            const int kb = ks*16;
            unsigned ah[2][4], al2[2][4];
            #pragma unroll
            for (int mt=0;mt<2;mt++){
                ldsm_x4(&Ah[32*wm + 16*mt + a_row][kb + a_co], ah[mt]);
                ldsm_x4(&Al[32*wm + 16*mt + a_row][kb + a_co], al2[mt]);
            }
            #pragma unroll
            for (int nt=0;nt<4;nt++){
                unsigned bh[2], blr[2];
                ldsm_x2(&Wh[32*wn + 8*nt + b_row][kb + b_co], bh);
                ldsm_x2(&Wl[32*wn + 8*nt + b_row][kb + b_co], blr);
                #pragma unroll
                for (int mt=0;mt<2;mt++){
                    mma16816(acc[mt][nt], ah[mt],  bh);
                    mma16816(acc[mt][nt], ah[mt],  blr);
                    mma16816(acc[mt][nt], al2[mt], bh);
                }
            }
        }
        __syncthreads();
    }
    #pragma unroll
    for (int mt=0;mt<2;mt++){
        #pragma unroll
        for (int nt=0;nt<4;nt++){
            int col = n0 + 32*wn + 8*nt + 2*tig;
            float bb0 = b1[col] + b2[col], bb1 = b1[col+1] + b2[col+1];
            int r0 = m0 + 32*wm + 16*mt + g;
            float2 v;
            v.x = acc[mt][nt][0] + bb0; v.y = acc[mt][nt][1] + bb1;
            *(float2*)&g_pre[(size_t)r0*G4_ + col] = v;
            v.x = acc[mt][nt][2] + bb0; v.y = acc[mt][nt][3] + bb1;
            *(float2*)&g_pre[(size_t)(r0+8)*G4_ + col] = v;
        }
    }
}

// ---------------------------------------------------------------------------
// Per-b-group barrier: lane-0-per-warp poll with nanosleep backoff
// (32x fewer pollers than R14, ~10x lower poll rate -> L2 decontended),
// __syncwarp broadcast keeps per-warp independent wake.
// ---------------------------------------------------------------------------
__device__ __forceinline__ void grid_bar_g(int grp, unsigned target){
    __syncthreads();                      // all this-CTA stores issued
    if (threadIdx.x == 0){
        __threadfence();                  // release
        atomicAdd(&g_bar4[grp << 5], 1u);
    }
    if ((threadIdx.x & 31) == 0){
        volatile unsigned* p = &g_bar4[grp << 5];
        while (*p < target) __nanosleep(64);
    }
    __syncwarp();
    __threadfence();                      // acquire (per thread)
}

// ---------------------------------------------------------------------------
// Persistent recurrence, HMMA split-f16 (PROVEN R14: per-warp h staging).
// ---------------------------------------------------------------------------
#define SMEM_REC 202240

template<int LAYER>
__global__ void __launch_bounds__(256, 1)
lstm_rec_k(const float* __restrict__ h0, const float* __restrict__ c0)
{
    const __half* Whh_hi = LAYER ? g_whh1hi : g_whh0hi;
    const __half* Whh_lo = LAYER ? g_whh1lo : g_whh0lo;

    extern __shared__ char smraw[];
    __half* Wh  = (__half*)smraw;            // [64][520]
    __half* Wl  = Wh + 64*520;               // [64][520]
    __half* Hh  = Wl + 64*520;               // [16][520]
    __half* Hl  = Hh + 16*520;               // [16][520]
    float*  P   = (float*)(Hl + 16*520);     // [8][16][68]
    float*  Csm = P + 8*16*68;               // [256]

    const int tid   = threadIdx.x;
    const int cta   = blockIdx.x;
    const int nbase = (cta & 31) << 4;
    const int bbase = (cta >> 5) << 4;
    const int grp   = cta >> 5;              // b-group id, 0..3
    const int bl = tid >> 4, nl = tid & 15;

    {   // install split h0 + c0
        size_t idx = (size_t)(bbase + bl)*H_ + (nbase + nl);
        Csm[tid] = c0[idx];
        float hv = h0[idx];
        __half hh = __float2half_rn(hv);
        g_hhi[idx] = hh;
        g_hlo[idx] = __float2half_rn(hv - __half2float(hh));
    }

    // preload W_hh tile (64 rows x 512) hi+lo from symbols (rows padded 520)
    for (int i = tid; i < 64*64; i += 256){
        int lr = i >> 6, cc = (i & 63) * 8;
        int grow = (lr >> 4)*H_ + nbase + (lr & 15);
        *(uint4*)&Wh[lr*520 + cc] = *(const uint4*)&Whh_hi[(size_t)grow*H_ + cc];
        *(uint4*)&Wl[lr*520 + cc] = *(const uint4*)&Whh_lo[(size_t)grow*H_ + cc];
    }

    const int wid = tid >> 5, lane = tid & 31;
    const int g   = lane >> 2, tig = lane & 3;
    const int a_row = lane & 15, a_co = (lane >> 4) * 8;
    const int b_row = lane & 7,  b_co = ((lane >> 3) & 1) * 8;
    // per-warp staging coords: 128 8-half chunks over 16 rows x 64 cols
    const int st_r  = lane >> 3;             // 0..3 base row (x4 below)
    const int st_c  = (lane & 7) * 8;        // 0..56 col within slice

    grid_bar_g(grp, 32);   // group's h0 visible; W smem loaded

    for (int t = 0; t < T_; ++t){
        const float* pb = g_pre + ((size_t)t*B_ + bbase + bl)*G4_ + nbase + nl;
        const float p_i = pb[0], p_f = pb[512], p_g = pb[1024], p_o = pb[1536];

        // PER-WARP stage of own h slice: cols [64*wid, 64*wid+64), 16 rows
        {
            const __half* shi = g_hhi + (size_t)t*BH_ + (size_t)bbase*H_ + 64*wid;
            const __half* slo = g_hlo + (size_t)t*BH_ + (size_t)bbase*H_ + 64*wid;
            #pragma unroll
            for (int j=0;j<4;j++){
                int r = st_r + 4*j;              // 0..15
                *(uint4*)&Hh[r*520 + 64*wid + st_c] =
                    *(const uint4*)&shi[(size_t)r*H_ + st_c];
                *(uint4*)&Hl[r*520 + 64*wid + st_c] =
                    *(const uint4*)&slo[(size_t)r*H_ + st_c];
            }
        }
        __syncwarp();

        float acc[8][4];
        #pragma unroll
        for (int j=0;j<8;j++)
            #pragma unroll
            for (int q=0;q<4;q++) acc[j][q] = 0.f;

        #pragma unroll
        for (int ks=0; ks<4; ks++){
            const int k0 = wid*64 + ks*16;
            unsigned ah[4], al2[4];
            ldsm_x4(&Hh[a_row*520 + k0 + a_co], ah);
            ldsm_x4(&Hl[a_row*520 + k0 + a_co], al2);
            #pragma unroll
            for (int j=0;j<8;j++){
                unsigned bh[2], blr[2];
                ldsm_x2(&Wh[(8*j + b_row)*520 + k0 + b_co], bh);
                ldsm_x2(&Wl[(8*j + b_row)*520 + k0 + b_co], blr);
                mma16816(acc[j], ah,  bh);
                mma16816(acc[j], ah,  blr);
                mma16816(acc[j], al2, bh);
            }
        }

        {
            float* Pw = P + wid*16*68;
            #pragma unroll
            for (int j=0;j<8;j++){
                float2 v;
                v.x = acc[j][0]; v.y = acc[j][1];
                *(float2*)&Pw[g*68 + 8*j + 2*tig] = v;
                v.x = acc[j][2]; v.y = acc[j][3];
                *(float2*)&Pw[(g+8)*68 + 8*j + 2*tig] = v;
            }
        }
        __syncthreads();

        {
            float s_i = p_i, s_f = p_f, s_g = p_g, s_o = p_o;
            #pragma unroll
            for (int w=0;w<8;w++){
                const float* Pw = P + w*16*68 + bl*68 + nl;
                s_i += Pw[0]; s_f += Pw[16]; s_g += Pw[32]; s_o += Pw[48];
            }
            float ii = sigf(s_i), ff = sigf(s_f);
            float gg = tanhf(s_g), oo = sigf(s_o);
            float c  = ff * Csm[tid] + ii * gg;
            Csm[tid] = c;
            float h  = oo * tanhf(c);
            size_t oidx = (size_t)(t+1)*BH_ + (size_t)(bbase+bl)*H_ + (nbase+nl);
            __half hh = __float2half_rn(h);
            g_hhi[oidx] = hh;
            g_hlo[oidx] = __float2half_rn(h - __half2float(hh));
        }
        grid_bar_g(grp, (unsigned)(t + 2) * 32);
    }
}

// ---------------------------------------------------------------------------
// out[b,o] = h_T[b,:] . W_out[o,:] + b_out[o]   (reconstruct hi+lo)
// ---------------------------------------------------------------------------
__global__ void __launch_bounds__(256)
out_head_k(const float* __restrict__ Wo, const float* __restrict__ bo,
           float* __restrict__ out)
{
    __shared__ float hs[H_];
    const int b = blockIdx.x;
    const __half* hih = g_hhi + (size_t)T_*BH_ + (size_t)b*H_;
    const __half* hil = g_hlo + (size_t)T_*BH_ + (size_t)b*H_;
    for (int k = threadIdx.x; k < H_; k += blockDim.x)
        hs[k] = __half2float(hih[k]) + __half2float(hil[k]);
    __syncthreads();
    const int o = threadIdx.x;
    const float* wr = Wo + (size_t)o * H_;
    float acc = 0.f;
    #pragma unroll 4
    for (int k = 0; k < H_; k += 4){
        float4 w = *reinterpret_cast<const float4*>(wr + k);
        acc = fmaf(hs[k  ], w.x, acc);
        acc = fmaf(hs[k+1], w.y, acc);
        acc = fmaf(hs[k+2], w.z, acc);
        acc = fmaf(hs[k+3], w.w, acc);
    }
    out[(size_t)b*O_ + o] = acc + bo[o];
}

// ---------------------------------------------------------------------------
extern "C" void kernel_launch(void* const* d_in, const int* in_sizes, int n_in,
                              void* d_out, int out_size)
{
    const float* x     = (const float*)d_in[0];
    const float* hc    = (const float*)d_in[1];
    const float* W_ih0 = (const float*)d_in[2];
    const float* W_hh0 = (const float*)d_in[3];
    const float* b_ih0 = (const float*)d_in[4];
    const float* b_hh0 = (const float*)d_in[5];
    const float* W_ih1 = (const float*)d_in[6];
    const float* W_hh1 = (const float*)d_in[7];
    const float* b_ih1 = (const float*)d_in[8];
    const float* b_hh1 = (const float*)d_in[9];
    const float* W_out = (const float*)d_in[10];
    const float* b_out = (const float*)d_in[11];
    float* out = (float*)d_out;

    const float* h0_l0 = hc;
    const float* h0_l1 = hc + BH_;
    const float* c0_l0 = hc + 2*BH_;
    const float* c0_l1 = hc + 3*BH_;

    // host-side attribute (function handle only; no data-symbol use on host)
    cudaFuncSetAttribute(lstm_rec_k<0>,
        cudaFuncAttributeMaxDynamicSharedMemorySize, SMEM_REC);
    cudaFuncSetAttribute(lstm_rec_k<1>,
        cudaFuncAttributeMaxDynamicSharedMemorySize, SMEM_REC);

    dim3 pgrid(G4_/64, (T_*B_)/128);     // (32, 256) = 8192 CTAs

    // One fused split for everything
    const int NTOT = NX_ + NW0_ + 3*NW_;
    split_all_k<<<(NTOT+255)/256, 256>>>(x, W_ih0, W_hh0, W_ih1, W_hh1);

    // Layer 0
    gemm_pre_mma<I_, 0><<<pgrid, 256>>>(b_ih0, b_hh0);
    reset_bar_k<<<1,32>>>();
    lstm_rec_k<0><<<GREC, 256, SMEM_REC>>>(h0_l0, c0_l0);

    // Layer 1: A = hs0 (device-split by layer-0 recurrence)
    gemm_pre_mma<H_, 1><<<pgrid, 256>>>(b_ih1, b_hh1);
    reset_bar_k<<<1,32>>>();
    lstm_rec_k<1><<<GREC, 256, SMEM_REC>>>(h0_l1, c0_l1);

    out_head_k<<<B_, 256>>>(W_out, b_out, out);
}

// round 16
// speedup vs baseline: 1.1467x; 1.1467x over previous
#include <cuda_runtime.h>
#include <cuda_fp16.h>
#include <math.h>

#define T_   512
#define B_   64
#define I_   256
#define H_   512
#define G4_  2048
#define O_   256
#define BH_  (B_*H_)
#define GREC 128

#define NX_   (T_*B_*I_)     // x elements
#define NW0_  (G4_*I_)       // W_ih0 elements
#define NW_   (G4_*H_)       // W_ih1 / W_hh* elements

// ---------------- scratch (device globals; no allocations anywhere) --------
// RULE (GB300/ATS pitfall): these symbols are referenced ONLY in device code.
static __device__ float    g_pre[(size_t)T_*B_*G4_];      // gate preacts
static __device__ __half   g_hhi[(size_t)(T_+1)*BH_];     // h hi (f16)
static __device__ __half   g_hlo[(size_t)(T_+1)*BH_];     // h lo (f16)
static __device__ __half   g_xhi[NX_],     g_xlo[NX_];    // split x
static __device__ __half   g_wih0hi[NW0_], g_wih0lo[NW0_];
static __device__ __half   g_whh0hi[NW_],  g_whh0lo[NW_];
static __device__ __half   g_wih1hi[NW_],  g_wih1lo[NW_];
static __device__ __half   g_whh1hi[NW_],  g_whh1lo[NW_];
static __device__ unsigned g_bar4[4*32];                  // per-b-group barriers

__device__ __forceinline__ float sigf(float x){ return 1.0f/(1.0f+expf(-x)); }

// One fused split: x, W_ih0, W_hh0, W_ih1, W_hh1 -> hi/lo symbol arrays
__global__ void split_all_k(const float* __restrict__ x,
                            const float* __restrict__ wih0,
                            const float* __restrict__ whh0,
                            const float* __restrict__ wih1,
                            const float* __restrict__ whh1)
{
    int i = blockIdx.x*blockDim.x + threadIdx.x;
    const float* src; __half* hi; __half* lo; int off;
    if (i < NX_)                        { src=x;    hi=g_xhi;    lo=g_xlo;    off=i; }
    else if (i < NX_+NW0_)              { src=wih0; hi=g_wih0hi; lo=g_wih0lo; off=i-NX_; }
    else if (i < NX_+NW0_+NW_)          { src=whh0; hi=g_whh0hi; lo=g_whh0lo; off=i-NX_-NW0_; }
    else if (i < NX_+NW0_+2*NW_)        { src=wih1; hi=g_wih1hi; lo=g_wih1lo; off=i-NX_-NW0_-NW_; }
    else if (i < NX_+NW0_+3*NW_)        { src=whh1; hi=g_whh1hi; lo=g_whh1lo; off=i-NX_-NW0_-2*NW_; }
    else return;
    float v = src[off];
    __half h = __float2half_rn(v);
    hi[off] = h;
    lo[off] = __float2half_rn(v - __half2float(h));
}

// ---------------- mma / async helpers (PROVEN) ------------------------------
__device__ __forceinline__ unsigned smem_u32(const void* p){
    return (unsigned)__cvta_generic_to_shared(p);
}
__device__ __forceinline__ void ldsm_x4(const void* p, unsigned* r){
    asm volatile("ldmatrix.sync.aligned.m8n8.x4.shared.b16 {%0,%1,%2,%3}, [%4];"
        : "=r"(r[0]),"=r"(r[1]),"=r"(r[2]),"=r"(r[3]) : "r"(smem_u32(p)) : "memory");
}
__device__ __forceinline__ void ldsm_x2(const void* p, unsigned* r){
    asm volatile("ldmatrix.sync.aligned.m8n8.x2.shared.b16 {%0,%1}, [%2];"
        : "=r"(r[0]),"=r"(r[1]) : "r"(smem_u32(p)) : "memory");
}
__device__ __forceinline__ void mma16816(float* c, const unsigned* a, const unsigned* b){
    asm volatile("mma.sync.aligned.m16n8k16.row.col.f32.f16.f16.f32 "
        "{%0,%1,%2,%3}, {%4,%5,%6,%7}, {%8,%9}, {%0,%1,%2,%3};"
        : "+f"(c[0]),"+f"(c[1]),"+f"(c[2]),"+f"(c[3])
        : "r"(a[0]),"r"(a[1]),"r"(a[2]),"r"(a[3]),"r"(b[0]),"r"(b[1]));
}
__device__ __forceinline__ void cp16(void* sdst, const void* gsrc){
    asm volatile("cp.async.ca.shared.global [%0], [%1], 16;"
        :: "r"(smem_u32(sdst)), "l"(gsrc) : "memory");
}
__device__ __forceinline__ void cp_commit(){
    asm volatile("cp.async.commit_group;" ::: "memory");
}
template<int N>
__device__ __forceinline__ void cp_wait(){
    asm volatile("cp.async.wait_group %0;" :: "n"(N) : "memory");
}

// ---------------------------------------------------------------------------
// Pre-GEMM, split-f16 HMMA, cp.async DOUBLE-BUFFERED staging.
// g_pre[m,n] = A[m,K] . W[n,K]^T + b1[n] + b2[n]
// CTA tile 128m x 64n, 8 warps (wm 0..3 x wn 0..1), warp tile 32x32.
// While tile i computes, tile i+1's 24 KB streams in via LDGSTS.
// Also resets the rec barrier counters (CTA (0,0)) -> drops 2 launches.
// ---------------------------------------------------------------------------
template<int K, int LAYER>
__global__ void __launch_bounds__(256, 2)
gemm_pre_mma(const float* __restrict__ b1, const float* __restrict__ b2)
{
    const __half* Ahi_g = LAYER ? (g_hhi + BH_) : g_xhi;
    const __half* Alo_g = LAYER ? (g_hlo + BH_) : g_xlo;
    const __half* Whi_g = LAYER ? g_wih1hi : g_wih0hi;
    const __half* Wlo_g = LAYER ? g_wih1lo : g_wih0lo;

    __shared__ __align__(16) __half Ah[2][128][40], Al[2][128][40];
    __shared__ __align__(16) __half Wh[2][64][40],  Wl[2][64][40];
    const int tid  = threadIdx.x;
    if (blockIdx.x == 0 && blockIdx.y == 0 && tid < 4)
        g_bar4[tid << 5] = 0u;            // reset rec barriers for this layer
    const int n0   = blockIdx.x * 64;
    const int m0   = blockIdx.y * 128;
    const int wid  = tid >> 5, lane = tid & 31;
    const int wm   = wid & 3,  wn   = wid >> 2;
    const int g    = lane >> 2, tig = lane & 3;
    const int a_row = lane & 15, a_co = (lane >> 4) * 8;
    const int b_row = lane & 7,  b_co = ((lane >> 3) & 1) * 8;

    // staging coords (16B granules)
    const int ar0 = tid >> 2,         ac0 = (tid & 3) * 8;          // A chunk 0
    const int ar1 = (tid + 256) >> 2, ac1 = (tid & 3) * 8;          // A chunk 1
    const int wr0 = tid >> 2,         wc0 = (tid & 3) * 8;          // W chunk

    float acc[2][4][4];
    #pragma unroll
    for (int mt=0;mt<2;mt++)
        #pragma unroll
        for (int nt=0;nt<4;nt++)
            #pragma unroll
            for (int q=0;q<4;q++) acc[mt][nt][q] = 0.f;

    constexpr int NIT = K / 32;

    // stage tile 0
    {
        cp16(&Ah[0][ar0][ac0], &Ahi_g[(size_t)(m0+ar0)*K + ac0]);
        cp16(&Ah[0][ar1][ac1], &Ahi_g[(size_t)(m0+ar1)*K + ac1]);
        cp16(&Al[0][ar0][ac0], &Alo_g[(size_t)(m0+ar0)*K + ac0]);
        cp16(&Al[0][ar1][ac1], &Alo_g[(size_t)(m0+ar1)*K + ac1]);
        if (tid < 64*4){ // 64 rows x 4 chunks = 256 -> all threads
            cp16(&Wh[0][wr0][wc0], &Whi_g[(size_t)(n0+wr0)*K + wc0]);
            cp16(&Wl[0][wr0][wc0], &Wlo_g[(size_t)(n0+wr0)*K + wc0]);
        }
        cp_commit();
    }

    for (int it = 0; it < NIT; ++it){
        const int buf = it & 1;
        if (it + 1 < NIT){
            const int nb = buf ^ 1;
            const int k0 = (it + 1) * 32;
            cp16(&Ah[nb][ar0][ac0], &Ahi_g[(size_t)(m0+ar0)*K + k0 + ac0]);
            cp16(&Ah[nb][ar1][ac1], &Ahi_g[(size_t)(m0+ar1)*K + k0 + ac1]);
            cp16(&Al[nb][ar0][ac0], &Alo_g[(size_t)(m0+ar0)*K + k0 + ac0]);
            cp16(&Al[nb][ar1][ac1], &Alo_g[(size_t)(m0+ar1)*K + k0 + ac1]);
            cp16(&Wh[nb][wr0][wc0], &Whi_g[(size_t)(n0+wr0)*K + k0 + wc0]);
            cp16(&Wl[nb][wr0][wc0], &Wlo_g[(size_t)(n0+wr0)*K + k0 + wc0]);
            cp_commit();
            cp_wait<1>();                 // tile `it` complete, tile it+1 in flight
        } else {
            cp_wait<0>();
        }
        __syncthreads();

        #pragma unroll
        for (int ks=0;ks<2;ks++){
            const int kb = ks*16;
            unsigned ah[2][4], al2[2][4];
            #pragma unroll
            for (int mt=0;mt<2;mt++){
                ldsm_x4(&Ah[buf][32*wm + 16*mt + a_row][kb + a_co], ah[mt]);
                ldsm_x4(&Al[buf][32*wm + 16*mt + a_row][kb + a_co], al2[mt]);
            }
            #pragma unroll
            for (int nt=0;nt<4;nt++){
                unsigned bh[2], blr[2];
                ldsm_x2(&Wh[buf][32*wn + 8*nt + b_row][kb + b_co], bh);
                ldsm_x2(&Wl[buf][32*wn + 8*nt + b_row][kb + b_co], blr);
                #pragma unroll
                for (int mt=0;mt<2;mt++){
                    mma16816(acc[mt][nt], ah[mt],  bh);
                    mma16816(acc[mt][nt], ah[mt],  blr);
                    mma16816(acc[mt][nt], al2[mt], bh);
                }
            }
        }
        __syncthreads();                  // ldsm done before buf overwritten
    }

    #pragma unroll
    for (int mt=0;mt<2;mt++){
        #pragma unroll
        for (int nt=0;nt<4;nt++){
            int col = n0 + 32*wn + 8*nt + 2*tig;
            float bb0 = b1[col] + b2[col], bb1 = b1[col+1] + b2[col+1];
            int r0 = m0 + 32*wm + 16*mt + g;
            float2 v;
            v.x = acc[mt][nt][0] + bb0; v.y = acc[mt][nt][1] + bb1;
            *(float2*)&g_pre[(size_t)r0*G4_ + col] = v;
            v.x = acc[mt][nt][2] + bb0; v.y = acc[mt][nt][3] + bb1;
            *(float2*)&g_pre[(size_t)(r0+8)*G4_ + col] = v;
        }
    }
}

// ---------------------------------------------------------------------------
// Per-b-group barrier (R14 PROVEN): all-thread immediate volatile poll,
// per-warp independent wake, no trailing block sync.
// ---------------------------------------------------------------------------
__device__ __forceinline__ void grid_bar_g(int grp, unsigned target){
    __syncthreads();                      // all this-CTA stores issued
    if (threadIdx.x == 0){
        __threadfence();                  // release
        atomicAdd(&g_bar4[grp << 5], 1u);
    }
    volatile unsigned* p = &g_bar4[grp << 5];
    while (*p < target) { }               // broadcast L2 poll
    __threadfence();                      // acquire (per thread)
}

// ---------------------------------------------------------------------------
// Persistent recurrence, HMMA split-f16 (PROVEN R14 verbatim).
// ---------------------------------------------------------------------------
#define SMEM_REC 202240

template<int LAYER>
__global__ void __launch_bounds__(256, 1)
lstm_rec_k(const float* __restrict__ h0, const float* __restrict__ c0)
{
    const __half* Whh_hi = LAYER ? g_whh1hi : g_whh0hi;
    const __half* Whh_lo = LAYER ? g_whh1lo : g_whh0lo;

    extern __shared__ char smraw[];
    __half* Wh  = (__half*)smraw;            // [64][520]
    __half* Wl  = Wh + 64*520;               // [64][520]
    __half* Hh  = Wl + 64*520;               // [16][520]
    __half* Hl  = Hh + 16*520;               // [16][520]
    float*  P   = (float*)(Hl + 16*520);     // [8][16][68]
    float*  Csm = P + 8*16*68;               // [256]

    const int tid   = threadIdx.x;
    const int cta   = blockIdx.x;
    const int nbase = (cta & 31) << 4;
    const int bbase = (cta >> 5) << 4;
    const int grp   = cta >> 5;              // b-group id, 0..3
    const int bl = tid >> 4, nl = tid & 15;

    {   // install split h0 + c0
        size_t idx = (size_t)(bbase + bl)*H_ + (nbase + nl);
        Csm[tid] = c0[idx];
        float hv = h0[idx];
        __half hh = __float2half_rn(hv);
        g_hhi[idx] = hh;
        g_hlo[idx] = __float2half_rn(hv - __half2float(hh));
    }

    // preload W_hh tile (64 rows x 512) hi+lo from symbols (rows padded 520)
    for (int i = tid; i < 64*64; i += 256){
        int lr = i >> 6, cc = (i & 63) * 8;
        int grow = (lr >> 4)*H_ + nbase + (lr & 15);
        *(uint4*)&Wh[lr*520 + cc] = *(const uint4*)&Whh_hi[(size_t)grow*H_ + cc];
        *(uint4*)&Wl[lr*520 + cc] = *(const uint4*)&Whh_lo[(size_t)grow*H_ + cc];
    }

    const int wid = tid >> 5, lane = tid & 31;
    const int g   = lane >> 2, tig = lane & 3;
    const int a_row = lane & 15, a_co = (lane >> 4) * 8;
    const int b_row = lane & 7,  b_co = ((lane >> 3) & 1) * 8;
    // per-warp staging coords: 128 8-half chunks over 16 rows x 64 cols
    const int st_r  = lane >> 3;             // 0..3 base row (x4 below)
    const int st_c  = (lane & 7) * 8;        // 0..56 col within slice

    grid_bar_g(grp, 32);   // group's h0 visible; W smem loaded

    for (int t = 0; t < T_; ++t){
        const float* pb = g_pre + ((size_t)t*B_ + bbase + bl)*G4_ + nbase + nl;
        const float p_i = pb[0], p_f = pb[512], p_g = pb[1024], p_o = pb[1536];

        // PER-WARP stage of own h slice: cols [64*wid, 64*wid+64), 16 rows
        {
            const __half* shi = g_hhi + (size_t)t*BH_ + (size_t)bbase*H_ + 64*wid;
            const __half* slo = g_hlo + (size_t)t*BH_ + (size_t)bbase*H_ + 64*wid;
            #pragma unroll
            for (int j=0;j<4;j++){
                int r = st_r + 4*j;              // 0..15
                *(uint4*)&Hh[r*520 + 64*wid + st_c] =
                    *(const uint4*)&shi[(size_t)r*H_ + st_c];
                *(uint4*)&Hl[r*520 + 64*wid + st_c] =
                    *(const uint4*)&slo[(size_t)r*H_ + st_c];
            }
        }
        __syncwarp();

        float acc[8][4];
        #pragma unroll
        for (int j=0;j<8;j++)
            #pragma unroll
            for (int q=0;q<4;q++) acc[j][q] = 0.f;

        #pragma unroll
        for (int ks=0; ks<4; ks++){
            const int k0 = wid*64 + ks*16;
            unsigned ah[4], al2[4];
            ldsm_x4(&Hh[a_row*520 + k0 + a_co], ah);
            ldsm_x4(&Hl[a_row*520 + k0 + a_co], al2);
            #pragma unroll
            for (int j=0;j<8;j++){
                unsigned bh[2], blr[2];
                ldsm_x2(&Wh[(8*j + b_row)*520 + k0 + b_co], bh);
                ldsm_x2(&Wl[(8*j + b_row)*520 + k0 + b_co], blr);
                mma16816(acc[j], ah,  bh);
                mma16816(acc[j], ah,  blr);
                mma16816(acc[j], al2, bh);
            }
        }

        {
            float* Pw = P + wid*16*68;
            #pragma unroll
            for (int j=0;j<8;j++){
                float2 v;
                v.x = acc[j][0]; v.y = acc[j][1];
                *(float2*)&Pw[g*68 + 8*j + 2*tig] = v;
                v.x = acc[j][2]; v.y = acc[j][3];
                *(float2*)&Pw[(g+8)*68 + 8*j + 2*tig] = v;
            }
        }
        __syncthreads();

        {
            float s_i = p_i, s_f = p_f, s_g = p_g, s_o = p_o;
            #pragma unroll
            for (int w=0;w<8;w++){
                const float* Pw = P + w*16*68 + bl*68 + nl;
                s_i += Pw[0]; s_f += Pw[16]; s_g += Pw[32]; s_o += Pw[48];
            }
            float ii = sigf(s_i), ff = sigf(s_f);
            float gg = tanhf(s_g), oo = sigf(s_o);
            float c  = ff * Csm[tid] + ii * gg;
            Csm[tid] = c;
            float h  = oo * tanhf(c);
            size_t oidx = (size_t)(t+1)*BH_ + (size_t)(bbase+bl)*H_ + (nbase+nl);
            __half hh = __float2half_rn(h);
            g_hhi[oidx] = hh;
            g_hlo[oidx] = __float2half_rn(h - __half2float(hh));
        }
        grid_bar_g(grp, (unsigned)(t + 2) * 32);
    }
}

// ---------------------------------------------------------------------------
// out[b,o] = h_T[b,:] . W_out[o,:] + b_out[o]   (reconstruct hi+lo)
// ---------------------------------------------------------------------------
__global__ void __launch_bounds__(256)
out_head_k(const float* __restrict__ Wo, const float* __restrict__ bo,
           float* __restrict__ out)
{
    __shared__ float hs[H_];
    const int b = blockIdx.x;
    const __half* hih = g_hhi + (size_t)T_*BH_ + (size_t)b*H_;
    const __half* hil = g_hlo + (size_t)T_*BH_ + (size_t)b*H_;
    for (int k = threadIdx.x; k < H_; k += blockDim.x)
        hs[k] = __half2float(hih[k]) + __half2float(hil[k]);
    __syncthreads();
    const int o = threadIdx.x;
    const float* wr = Wo + (size_t)o * H_;
    float acc = 0.f;
    #pragma unroll 4
    for (int k = 0; k < H_; k += 4){
        float4 w = *reinterpret_cast<const float4*>(wr + k);
        acc = fmaf(hs[k  ], w.x, acc);
        acc = fmaf(hs[k+1], w.y, acc);
        acc = fmaf(hs[k+2], w.z, acc);
        acc = fmaf(hs[k+3], w.w, acc);
    }
    out[(size_t)b*O_ + o] = acc + bo[o];
}

// ---------------------------------------------------------------------------
extern "C" void kernel_launch(void* const* d_in, const int* in_sizes, int n_in,
                              void* d_out, int out_size)
{
    const float* x     = (const float*)d_in[0];
    const float* hc    = (const float*)d_in[1];
    const float* W_ih0 = (const float*)d_in[2];
    const float* W_hh0 = (const float*)d_in[3];
    const float* b_ih0 = (const float*)d_in[4];
    const float* b_hh0 = (const float*)d_in[5];
    const float* W_ih1 = (const float*)d_in[6];
    const float* W_hh1 = (const float*)d_in[7];
    const float* b_ih1 = (const float*)d_in[8];
    const float* b_hh1 = (const float*)d_in[9];
    const float* W_out = (const float*)d_in[10];
    const float* b_out = (const float*)d_in[11];
    float* out = (float*)d_out;

    const float* h0_l0 = hc;
    const float* h0_l1 = hc + BH_;
    const float* c0_l0 = hc + 2*BH_;
    const float* c0_l1 = hc + 3*BH_;

    // host-side attribute (function handle only; no data-symbol use on host)
    cudaFuncSetAttribute(lstm_rec_k<0>,
        cudaFuncAttributeMaxDynamicSharedMemorySize, SMEM_REC);
    cudaFuncSetAttribute(lstm_rec_k<1>,
        cudaFuncAttributeMaxDynamicSharedMemorySize, SMEM_REC);

    dim3 pgrid(G4_/64, (T_*B_)/128);     // (32, 256) = 8192 CTAs

    // One fused split for everything
    const int NTOT = NX_ + NW0_ + 3*NW_;
    split_all_k<<<(NTOT+255)/256, 256>>>(x, W_ih0, W_hh0, W_ih1, W_hh1);

    // Layer 0 (pre kernel also resets rec barriers)
    gemm_pre_mma<I_, 0><<<pgrid, 256>>>(b_ih0, b_hh0);
    lstm_rec_k<0><<<GREC, 256, SMEM_REC>>>(h0_l0, c0_l0);

    // Layer 1: A = hs0 (device-split by layer-0 recurrence)
    gemm_pre_mma<H_, 1><<<pgrid, 256>>>(b_ih1, b_hh1);
    lstm_rec_k<1><<<GREC, 256, SMEM_REC>>>(h0_l1, c0_l1);

    out_head_k<<<B_, 256>>>(W_out, b_out, out);
}